// round 8
// baseline (speedup 1.0000x reference)
#include <cuda_runtime.h>

#define NOBJ   4096
#define DIM    1024
#define DIM2   2048
#define NREL   8
#define NPAIR  65536
#define NBLK   148
#define NTHR   384
#define NWARPS (NBLK * (NTHR / 32))   // 1776
#define NTIDS  (NBLK * NTHR)          // 56832

// Scratch (device globals — no allocation allowed)
__device__ float g_M[NREL * DIM2];   // fused weight M = W2 @ W1, 64 KB
__device__ float g_c[NREL];          // fused bias c = W2@b1 + b2
__device__ float g_U[NOBJ * 16];     // per-object projections, 256 KB
                                     //   [o][0:8]  = f·M[:, :1024]ᵀ
                                     //   [o][8:16] = f·M[:, 1024:]ᵀ + c

// Grid barrier state: monotonic across graph replays (each launch adds
// exactly 2*gridDim.x arrivals and 2 epochs; no reset needed).
__device__ unsigned g_arrive_cnt = 0;
__device__ volatile unsigned g_epoch_cnt = 0;

// Packed fp32x2 FMA: d = a*b + d elementwise on (lo,hi) pairs.
__device__ __forceinline__ void ffma2(unsigned long long& acc,
                                      unsigned long long a,
                                      unsigned long long b) {
    asm("fma.rn.f32x2 %0, %1, %2, %0;" : "+l"(acc) : "l"(a), "l"(b));
}

__device__ __forceinline__ float4 f4fma(float s, float4 v, float4 a) {
    a.x += s * v.x; a.y += s * v.y; a.z += s * v.z; a.w += s * v.w;
    return a;
}

__device__ __forceinline__ void grid_barrier(unsigned target_epoch) {
    __syncthreads();
    if (threadIdx.x == 0) {
        __threadfence();
        unsigned prev = atomicAdd(&g_arrive_cnt, 1u);
        if ((prev + 1u) % (unsigned)gridDim.x == 0u)
            g_epoch_cnt = g_epoch_cnt + 1u;      // sole writer per barrier
        while (g_epoch_cnt < target_epoch) __nanosleep(64);
        __threadfence();
    }
    __syncthreads();
}

// ---------------------------------------------------------------------------
// One persistent kernel: M (+c) -> barrier -> U -> barrier -> gather.
// 148 blocks x 384 threads, all resident in wave 1.
// ---------------------------------------------------------------------------
__global__ void __launch_bounds__(NTHR) fused_kernel(const float* __restrict__ feats,
                                                     const int*   __restrict__ pairs,
                                                     const float* __restrict__ W1,
                                                     const float* __restrict__ b1,
                                                     const float* __restrict__ W2,
                                                     const float* __restrict__ b2,
                                                     float* __restrict__ out) {
    __shared__ float  sW2[NREL * DIM];   // 32 KB
    __shared__ float4 sAcc[8 * 32];      // 4 KB  [warp][r*4+jq]
    __shared__ unsigned s_eb;

    const int bid = blockIdx.x;
    const int tx  = threadIdx.x;
    const int lane = tx & 31;

    if (tx == 0) s_eb = g_epoch_cnt;     // epoch base (stable: no barrier can
                                         // complete before every block reads it)
    // ---- Phase A: M = W2 @ W1 (blocks 0..127), c (block 128) ----
    if (bid < 128 && tx < 256) {         // stage full W2 (2048 float4)
        const float4* __restrict__ W24 = (const float4*)W2;
        float4* sW24 = (float4*)sW2;
#pragma unroll
        for (int u = 0; u < 8; u++) sW24[tx + u * 256] = __ldg(&W24[tx + u * 256]);
    }
    __syncthreads();

    if (bid < 128 && tx < 256) {
        const int jq = tx & 3;           // float4 col within the 16-j chunk
        const int ir = tx >> 2;          // 0..63
        const int jb4 = bid * 4;         // block's float4 col base (512 total)
        const float4* __restrict__ W14 = (const float4*)W1;

        float4 acc[NREL];
#pragma unroll
        for (int r = 0; r < NREL; r++) acc[r] = make_float4(0.f, 0.f, 0.f, 0.f);

#pragma unroll 1
        for (int ib = 0; ib < 4; ib++) { // 4 batches x 4 independent loads
            float4 w1v[4];
#pragma unroll
            for (int u = 0; u < 4; u++) {
                const int i = (ib * 4 + u) * 64 + ir;
                w1v[u] = __ldg(&W14[i * 512 + jb4 + jq]);
            }
#pragma unroll
            for (int u = 0; u < 4; u++) {
                const int i = (ib * 4 + u) * 64 + ir;
#pragma unroll
                for (int r = 0; r < NREL; r++)
                    acc[r] = f4fma(sW2[r * DIM + i], w1v[u], acc[r]);
            }
        }
        // warp butterfly over the 8 ir-values within the warp (lane bits 2..4)
#pragma unroll
        for (int off = 4; off <= 16; off <<= 1) {
#pragma unroll
            for (int r = 0; r < NREL; r++) {
                acc[r].x += __shfl_xor_sync(0xffffffffu, acc[r].x, off);
                acc[r].y += __shfl_xor_sync(0xffffffffu, acc[r].y, off);
                acc[r].z += __shfl_xor_sync(0xffffffffu, acc[r].z, off);
                acc[r].w += __shfl_xor_sync(0xffffffffu, acc[r].w, off);
            }
        }
        if (lane < 4) {                  // one lane per jq holds warp total
            const int w = tx >> 5;       // 0..7
#pragma unroll
            for (int r = 0; r < NREL; r++) sAcc[w * 32 + r * 4 + lane] = acc[r];
        }
    }
    __syncthreads();
    if (bid < 128 && tx < 32) {          // fixed-order reduce over 8 warps
        const int r = tx >> 2, jq = tx & 3;
        float4 s = sAcc[0 * 32 + r * 4 + jq];
#pragma unroll
        for (int w = 1; w < 8; w++) {
            float4 p = sAcc[w * 32 + r * 4 + jq];
            s.x += p.x; s.y += p.y; s.z += p.z; s.w += p.w;
        }
        ((float4*)g_M)[r * 512 + bid * 4 + jq] = s;
    }
    if (bid == 128 && tx < 256) {        // c[r] = W2[r]·b1 + b2[r]
        const int w = tx >> 5;
        float t = 0.f;
        for (int i = lane; i < DIM; i += 32) t += b1[i] * __ldg(&W2[w * DIM + i]);
#pragma unroll
        for (int off = 16; off; off >>= 1)
            t += __shfl_xor_sync(0xffffffffu, t, off);
        if (lane == 0) g_c[w] = t + b2[w];
    }

    grid_barrier(s_eb + 1);

    // ---- Phase B: U table. 2048 tasks (pair x half) over 1776 warps ----
    {
        const int wg = bid * (NTHR / 32) + (tx >> 5);   // 0..1775
        const longlong2* __restrict__ F2 = (const longlong2*)feats;
        const longlong2* __restrict__ M2 = (const longlong2*)g_M;

#pragma unroll 1
        for (int task = wg; task < 2048; task += NWARPS) {
            const int pair = task >> 1;
            const int half = task & 1;
            const int obase = pair * 4;
            const int jbase = half * 256;

            unsigned long long acc[4][8];
#pragma unroll
            for (int k = 0; k < 4; k++)
#pragma unroll
                for (int j = 0; j < 8; j++) acc[k][j] = 0ull;

#pragma unroll 1
            for (int t = 0; t < 8; t++) {
                const int idx = t * 32 + lane;
                unsigned long long fa[4], fb[4];
#pragma unroll
                for (int k = 0; k < 4; k++) {
                    longlong2 fv = __ldg(F2 + (obase + k) * 256 + idx);
                    fa[k] = (unsigned long long)fv.x;
                    fb[k] = (unsigned long long)fv.y;
                }
#pragma unroll
                for (int j = 0; j < 8; j++) {
                    longlong2 mv = __ldg(M2 + j * 512 + jbase + idx);
                    const unsigned long long ma = (unsigned long long)mv.x;
                    const unsigned long long mb = (unsigned long long)mv.y;
#pragma unroll
                    for (int k = 0; k < 4; k++) {
                        ffma2(acc[k][j], fa[k], ma);
                        ffma2(acc[k][j], fb[k], mb);
                    }
                }
            }

            float v[32];
#pragma unroll
            for (int k = 0; k < 4; k++)
#pragma unroll
                for (int j = 0; j < 8; j++) {
                    float2 p = *(float2*)&acc[k][j];
                    v[k * 8 + j] = p.x + p.y;
                }

            int nv = 32;                 // butterfly fold: 31 shfl total
#pragma unroll
            for (int d = 1; d < 32; d <<= 1) {
                nv >>= 1;
                const bool up = (lane & d) != 0;
#pragma unroll
                for (int i = 0; i < 16; i++) {
                    if (i < nv) {
                        float send = up ? v[i] : v[i + nv];
                        float recv = __shfl_xor_sync(0xffffffffu, send, d);
                        v[i] = (up ? v[i + nv] : v[i]) + recv;
                    }
                }
            }

            const int vi = __brev(lane) >> 27;   // bitrev5
            const int k = vi >> 3;
            const int j = vi & 7;
            const float bias = half ? g_c[j] : 0.f;
            g_U[(obase + k) * 16 + half * 8 + j] = v[0] + bias;
        }
    }

    grid_barrier(s_eb + 2);

    // ---- Phase C: gather. out[p] = U[s][0:8] + U[o][8:16] ----
    {
        const int tid = bid * NTHR + tx;            // 0..56831
        const float4* __restrict__ U4 = (const float4*)g_U;
        float4* __restrict__ O4 = (float4*)out;
#pragma unroll 1
        for (int p = tid; p < NPAIR; p += NTIDS) {  // 1-2 iterations
            int2 pr = __ldg(&((const int2*)pairs)[p]);
            float4 a0 = __ldg(&U4[pr.x * 4 + 0]);
            float4 a1 = __ldg(&U4[pr.x * 4 + 1]);
            float4 b0 = __ldg(&U4[pr.y * 4 + 2]);
            float4 b1 = __ldg(&U4[pr.y * 4 + 3]);
            float4 r0, r1;
            r0.x = a0.x + b0.x;  r0.y = a0.y + b0.y;
            r0.z = a0.z + b0.z;  r0.w = a0.w + b0.w;
            r1.x = a1.x + b1.x;  r1.y = a1.y + b1.y;
            r1.z = a1.z + b1.z;  r1.w = a1.w + b1.w;
            O4[p * 2 + 0] = r0;
            O4[p * 2 + 1] = r1;
        }
    }
}

extern "C" void kernel_launch(void* const* d_in, const int* in_sizes, int n_in,
                              void* d_out, int out_size) {
    const float* feats = (const float*)d_in[0];   // (4096, 1024) f32
    const int*   pairs = (const int*)d_in[1];     // (65536, 2) i32
    const float* W1    = (const float*)d_in[2];   // (1024, 2048) f32
    const float* b1    = (const float*)d_in[3];   // (1024,) f32
    const float* W2    = (const float*)d_in[4];   // (8, 1024) f32
    const float* b2    = (const float*)d_in[5];   // (8,) f32
    float*       out   = (float*)d_out;           // (65536, 8) f32

    fused_kernel<<<NBLK, NTHR>>>(feats, pairs, W1, b1, W2, b2, out);
}